// round 4
// baseline (speedup 1.0000x reference)
#include <cuda_runtime.h>
#include <cstdint>

#define N_NODES 50000
#define N_EDGES 800000
#define IN_DIM  256
#define HIDDEN  128
#define OUT_DIM 64
#define NEG_SLOPE 0.1f

// Scratch (device globals: allocation-free rule)
__device__ __align__(16) float g_h0[N_NODES * HIDDEN];  // activations
__device__ __align__(16) float g_h1[N_NODES * HIDDEN];  // transformed feats
__device__ float g_dinv[N_NODES];
__device__ int   g_cnt[N_NODES];
__device__ int   g_fill[N_NODES];
__device__ int   g_rowptr[N_NODES + 1];
__device__ int   g_srcidx[N_EDGES];
__device__ int   g_is64;

#define BUF_EXT 0
#define BUF_H0  1

// ---------------------------------------------------------------------------
// Init + dtype detection
// ---------------------------------------------------------------------------
__global__ void k_init() {
    int i = blockIdx.x * blockDim.x + threadIdx.x;
    if (i < N_NODES) { g_cnt[i] = 0; g_fill[i] = 0; }
    if (i == 0) g_is64 = 1;
}

// If edge_index is int64 with values in [0, 50000), every odd 32-bit word is 0.
// If it's int32, odd words are src values — overwhelmingly nonzero.
__global__ void k_detect(const unsigned* __restrict__ e) {
    int i = blockIdx.x * blockDim.x + threadIdx.x;
    if (i < 4096) {                       // reads first 32KB: in-bounds either way
        if (e[2 * i + 1] != 0u) g_is64 = 0;
    }
}

__device__ __forceinline__ int edge_src(const void* ei, int e) {
    return g_is64 ? (int)((const long long*)ei)[e] : ((const int*)ei)[e];
}
__device__ __forceinline__ int edge_dst(const void* ei, int e) {
    return g_is64 ? (int)((const long long*)ei)[N_EDGES + e]
                  : ((const int*)ei)[N_EDGES + e];
}

// ---------------------------------------------------------------------------
// CSR build: histogram -> dinv -> scan -> placement
// ---------------------------------------------------------------------------
__global__ void k_hist(const void* __restrict__ ei) {
    int e = blockIdx.x * blockDim.x + threadIdx.x;
    if (e < N_EDGES) atomicAdd(&g_cnt[edge_dst(ei, e)], 1);
}

__global__ void k_dinv() {
    int i = blockIdx.x * blockDim.x + threadIdx.x;
    if (i < N_NODES) g_dinv[i] = rsqrtf((float)g_cnt[i] + 1.0f);  // +1 self loop
}

// single-block exclusive scan of g_cnt -> g_rowptr (1024 threads, 49 elems each)
__global__ __launch_bounds__(1024) void k_scan() {
    __shared__ int ssum[1024];
    const int t = threadIdx.x;
    const int CH = 49;                         // 49*1024 = 50176 >= 50000
    int base = t * CH;
    int s = 0;
    for (int j = 0; j < CH; j++) {
        int idx = base + j;
        if (idx < N_NODES) s += g_cnt[idx];
    }
    ssum[t] = s;
    __syncthreads();
    for (int off = 1; off < 1024; off <<= 1) { // Hillis-Steele inclusive scan
        int v = (t >= off) ? ssum[t - off] : 0;
        __syncthreads();
        ssum[t] += v;
        __syncthreads();
    }
    int ex = (t == 0) ? 0 : ssum[t - 1];
    for (int j = 0; j < CH; j++) {
        int idx = base + j;
        if (idx < N_NODES) { g_rowptr[idx] = ex; ex += g_cnt[idx]; }
    }
    if (t == 1023) g_rowptr[N_NODES] = ssum[1023];
}

__global__ void k_place(const void* __restrict__ ei) {
    int e = blockIdx.x * blockDim.x + threadIdx.x;
    if (e < N_EDGES) {
        int s = edge_src(ei, e);
        int d = edge_dst(ei, e);
        int pos = g_rowptr[d] + atomicAdd(&g_fill[d], 1);
        g_srcidx[pos] = s;
    }
}

// ---------------------------------------------------------------------------
// Tiled fp32 GEMM:  out[M,C] = A[M,K] @ W[K,C]
// MODE 0: +bias, leaky  (encoder, A=ext x, out=g_h0)
// MODE 1: +bias         (decoder, A=g_h0,  out=ext)
// MODE 3: plain         (conv,    A=g_h0,  out=g_h1)
// ---------------------------------------------------------------------------
template <int K, int C, int MODE, int SRC>
__global__ __launch_bounds__(256)
void k_gemm(const float* __restrict__ Aext, const float* __restrict__ W,
            const float* __restrict__ bias, float* __restrict__ Oext)
{
    const float* A   = (SRC == BUF_H0) ? g_h0 : Aext;
    float*       out = (MODE == 0) ? g_h0 : ((MODE == 3) ? g_h1 : Oext);

    constexpr int TM = 32, TK = 64;
    constexpr int CG = C / 4;
    constexpr int RG = 256 / CG;
    constexpr int RPT = TM / RG;

    __shared__ float xs[TM][TK];
    __shared__ float ws[TK][C];

    const int m0  = blockIdx.x * TM;
    const int tid = threadIdx.x;
    const int cg  = tid % CG;
    const int rg  = tid / CG;

    float acc[RPT][4];
#pragma unroll
    for (int r = 0; r < RPT; r++)
#pragma unroll
        for (int j = 0; j < 4; j++) acc[r][j] = 0.0f;

    for (int kt = 0; kt < K; kt += TK) {
#pragma unroll
        for (int i = tid; i < TM * TK / 4; i += 256) {
            int row = (i * 4) / TK, col = (i * 4) % TK;
            int m = m0 + row;
            float4 v = make_float4(0.f, 0.f, 0.f, 0.f);
            if (m < N_NODES)
                v = *(const float4*)&A[(size_t)m * K + kt + col];
            *(float4*)&xs[row][col] = v;
        }
#pragma unroll
        for (int i = tid; i < TK * C / 4; i += 256) {
            int row = (i * 4) / C, col = (i * 4) % C;
            *(float4*)&ws[row][col] = *(const float4*)&W[(size_t)(kt + row) * C + col];
        }
        __syncthreads();

#pragma unroll
        for (int k = 0; k < TK; k++) {
            float4 wv = *(const float4*)&ws[k][cg * 4];
#pragma unroll
            for (int r = 0; r < RPT; r++) {
                float a = xs[rg * RPT + r][k];
                acc[r][0] += a * wv.x;
                acc[r][1] += a * wv.y;
                acc[r][2] += a * wv.z;
                acc[r][3] += a * wv.w;
            }
        }
        __syncthreads();
    }

#pragma unroll
    for (int r = 0; r < RPT; r++) {
        int m = m0 + rg * RPT + r;
        if (m >= N_NODES) continue;
        int c = cg * 4;
        float4 v = make_float4(acc[r][0], acc[r][1], acc[r][2], acc[r][3]);
        if (MODE == 0 || MODE == 1) {
            v.x += bias[c]; v.y += bias[c + 1]; v.z += bias[c + 2]; v.w += bias[c + 3];
        }
        if (MODE == 0) {
            v.x = v.x > 0.f ? v.x : NEG_SLOPE * v.x;
            v.y = v.y > 0.f ? v.y : NEG_SLOPE * v.y;
            v.z = v.z > 0.f ? v.z : NEG_SLOPE * v.z;
            v.w = v.w > 0.f ? v.w : NEG_SLOPE * v.w;
        }
        *(float4*)&out[(size_t)m * C + c] = v;
    }
}

// ---------------------------------------------------------------------------
// Aggregation (gather): one warp per dst node, lane handles 4 of 128 dims.
// h0[d] = leaky( sum_{e in CSR(d)} h1[src]*dinv[src]*dinv[d]
//                + h1[d]*dinv[d]^2 + bias )
// ---------------------------------------------------------------------------
__global__ __launch_bounds__(256)
void k_gather(const float* __restrict__ bias)
{
    int d    = (blockIdx.x * blockDim.x + threadIdx.x) >> 5;
    int lane = threadIdx.x & 31;
    if (d >= N_NODES) return;

    float dd  = g_dinv[d];
    int   beg = g_rowptr[d], end = g_rowptr[d + 1];

    float4 v = *(const float4*)&g_h1[(size_t)d * HIDDEN + lane * 4];
    float  w0 = dd * dd;
    float4 acc = make_float4(v.x * w0, v.y * w0, v.z * w0, v.w * w0);

    for (int j = beg; j < end; j++) {
        int   s = g_srcidx[j];
        float w = g_dinv[s] * dd;
        float4 u = *(const float4*)&g_h1[(size_t)s * HIDDEN + lane * 4];
        acc.x += u.x * w; acc.y += u.y * w; acc.z += u.z * w; acc.w += u.w * w;
    }

    int c = lane * 4;
    acc.x += bias[c];     acc.y += bias[c + 1];
    acc.z += bias[c + 2]; acc.w += bias[c + 3];
    acc.x = acc.x > 0.f ? acc.x : NEG_SLOPE * acc.x;
    acc.y = acc.y > 0.f ? acc.y : NEG_SLOPE * acc.y;
    acc.z = acc.z > 0.f ? acc.z : NEG_SLOPE * acc.z;
    acc.w = acc.w > 0.f ? acc.w : NEG_SLOPE * acc.w;
    *(float4*)&g_h0[(size_t)d * HIDDEN + c] = acc;
}

// ---------------------------------------------------------------------------
// Launch
// ---------------------------------------------------------------------------
extern "C" void kernel_launch(void* const* d_in, const int* in_sizes, int n_in,
                              void* d_out, int out_size)
{
    const float* x      = (const float*)d_in[0];
    const void*  ei     = d_in[1];                 // int32 or int64, detected
    const float* enc_W  = (const float*)d_in[2];
    const float* enc_b  = (const float*)d_in[3];
    const float* conv_W = (const float*)d_in[4];   // [2,128,128]
    const float* conv_b = (const float*)d_in[5];   // [2,128]
    const float* dec_W  = (const float*)d_in[6];
    const float* dec_b  = (const float*)d_in[7];
    float*       out    = (float*)d_out;

    const int nodeBlocks = (N_NODES + 255) / 256;
    const int edgeBlocks = (N_EDGES + 255) / 256;
    const int gemmBlocks = (N_NODES + 31) / 32;
    const int gathBlocks = (N_NODES * 32 + 255) / 256;

    k_init<<<nodeBlocks, 256>>>();
    k_detect<<<16, 256>>>((const unsigned*)ei);
    k_hist<<<edgeBlocks, 256>>>(ei);
    k_dinv<<<nodeBlocks, 256>>>();
    k_scan<<<1, 1024>>>();
    k_place<<<edgeBlocks, 256>>>(ei);

    // encoder: h0 = leaky(x @ enc_W + enc_b)
    k_gemm<IN_DIM, HIDDEN, 0, BUF_EXT><<<gemmBlocks, 256>>>(x, enc_W, enc_b, nullptr);

    for (int l = 0; l < 2; l++) {
        const float* W = conv_W + (size_t)l * HIDDEN * HIDDEN;
        const float* b = conv_b + (size_t)l * HIDDEN;
        k_gemm<HIDDEN, HIDDEN, 3, BUF_H0><<<gemmBlocks, 256>>>(nullptr, W, nullptr, nullptr);
        k_gather<<<gathBlocks, 256>>>(b);
    }

    // decoder: out = h0 @ dec_W + dec_b
    k_gemm<HIDDEN, OUT_DIM, 1, BUF_H0><<<gemmBlocks, 256>>>(nullptr, dec_W, dec_b, out);
}